// round 16
// baseline (speedup 1.0000x reference)
#include <cuda_runtime.h>
#include <cuda_fp16.h>
#include <cstdint>

#define M_TOTAL 16384
#define K_DIM   2048
#define N_DIM   2048
#define JTOT    64
#define SCALE_F 2.0f

// ---------------- device scratch ------------------------------------------
__device__ __align__(16) __half g_xh[(size_t)M_TOTAL * K_DIM];   // x fp16
__device__ __align__(16) __half g_wh[(size_t)N_DIM * K_DIM];     // W fp16
__device__ __align__(16) __half g_ah[(size_t)JTOT * K_DIM];      // Acat fp16
__device__ __align__(16) __half g_g [(size_t)M_TOTAL * JTOT];    // G fp16
__device__ __align__(16) __half g_bh[(size_t)N_DIM * JTOT];      // Bcat fp16

// ---------------- helpers --------------------------------------------------
static __device__ __forceinline__ uint32_t smem_u32(const void* p) {
    uint32_t a;
    asm("{ .reg .u64 t; cvta.to.shared.u64 t, %1; cvt.u32.u64 %0, t; }"
        : "=r"(a) : "l"(p));
    return a;
}
static __device__ __forceinline__ uint32_t f16x2(float a, float b) {
    uint32_t r;
    asm("cvt.rn.f16x2.f32 %0, %1, %2;" : "=r"(r) : "f"(b), "f"(a));
    return r;
}
static __device__ __forceinline__ void cpasync16(uint32_t dst, const void* src) {
    asm volatile("cp.async.cg.shared.global [%0], [%1], 16;"
                 :: "r"(dst), "l"(src) : "memory");
}
#define CP_COMMIT() asm volatile("cp.async.commit_group;" ::: "memory")
#define CP_WAIT1()  asm volatile("cp.async.wait_group 1;" ::: "memory")
#define CP_WAIT2()  asm volatile("cp.async.wait_group 2;" ::: "memory")

#define LDSM4(r, addr)                                                       \
    asm volatile("ldmatrix.sync.aligned.m8n8.x4.shared.b16 {%0,%1,%2,%3}, [%4];" \
        : "=r"((r)[0]), "=r"((r)[1]), "=r"((r)[2]), "=r"((r)[3]) : "r"(addr))

#define MMA16816(c, a, b)                                                    \
    asm volatile(                                                            \
        "mma.sync.aligned.m16n8k16.row.col.f32.f16.f16.f32 "                 \
        "{%0,%1,%2,%3}, {%4,%5,%6,%7}, {%8,%9}, {%0,%1,%2,%3};"              \
        : "+f"((c)[0]), "+f"((c)[1]), "+f"((c)[2]), "+f"((c)[3])             \
        : "r"((a)[0]), "r"((a)[1]), "r"((a)[2]), "r"((a)[3]),                \
          "r"((b)[0]), "r"((b)[1]))

// 128B-row SW128 swizzle (BK=64 tiles)
static __device__ __forceinline__ uint32_t sw128(int row, int chunk) {
    return (uint32_t)(row * 128 + ((chunk ^ (row & 7)) << 4));
}

// ---------------- conversion sizes -----------------------------------------
#define NX8 4194304     // x:  uint4 items (8 fp32 each)
#define NW8 524288      // W:  uint4 items
#define NA8 16384       // A:  uint4 items
#define NB  131072      // Bw: scalar items
#define CONV_XA_TOTAL (NX8 + NA8)

static __device__ __forceinline__ uint4 cvt8s(const float4* s) {
    float4 v0 = __ldcs(s);
    float4 v1 = __ldcs(s + 1);
    uint4 o;
    o.x = f16x2(v0.x, v0.y);
    o.y = f16x2(v0.z, v0.w);
    o.z = f16x2(v1.x, v1.y);
    o.w = f16x2(v1.z, v1.w);
    return o;
}

// ---------------- conv kernel: x + Acat only (G's inputs) ------------------
__global__ void conv_xa_kernel(const float* __restrict__ x,
                               const float* __restrict__ A)
{
    int i = blockIdx.x * blockDim.x + threadIdx.x;
    if (i < NX8) {
        ((uint4*)g_xh)[i] = cvt8s(((const float4*)x) + 2 * (size_t)i);
        return;
    }
    i -= NX8;
    if (i < NA8)
        ((uint4*)g_ah)[i] = cvt8s(((const float4*)A) + 2 * (size_t)i);
}

// ---------------- G kernel + embedded W/Bw converter blocks ----------------
#define G_BLOCKS     256
#define GCONV_BLOCKS 188
#define G_STAGE  16384
#define G_SMEM   (3 * G_STAGE)

__global__ __launch_bounds__(256, 3) void g_gemm_kernel(
    const float* __restrict__ mask,
    const float* __restrict__ W,
    const float* __restrict__ Bw)
{
    extern __shared__ __align__(128) char smem[];
    const int tid = threadIdx.x;

    if (blockIdx.x >= G_BLOCKS) {
        const int stride = GCONV_BLOCKS * 256;
        int base = (blockIdx.x - G_BLOCKS) * 256 + tid;
        for (int i = base; i < NW8; i += stride)
            ((uint4*)g_wh)[i] = cvt8s(((const float4*)W) + 2 * (size_t)i);
        for (int i = base; i < NB; i += stride) {
            int na = i >> 15;
            int n  = (i >> 4) & 2047;
            int r  = i & 15;
            g_bh[(size_t)n * JTOT + na * 16 + r] = __float2half_rn(__ldcs(Bw + i));
        }
        return;
    }

    const uint32_t sb = smem_u32(smem);
    const int wid = tid >> 5, lane = tid & 31;
    const int warp_m = wid >> 2, warp_n = wid & 3;
    const int m0 = blockIdx.x * 64;

    float acc[2][2][4];
#pragma unroll
    for (int i = 0; i < 2; i++)
#pragma unroll
        for (int j = 0; j < 2; j++)
#pragma unroll
            for (int p = 0; p < 4; p++) acc[i][j][p] = 0.f;

    auto load_stage = [&](int c, int st_i) {
        uint32_t st = sb + (uint32_t)st_i * G_STAGE;
        const __half* px  = g_xh + (size_t)m0 * K_DIM + c * 64;
        const __half* pah = g_ah + (size_t)c * 64;
#pragma unroll
        for (int q = 0; q < 2; q++) {
            int idx = tid + q * 256;
            int r = idx >> 3, ch = idx & 7;
            cpasync16(st + sw128(r, ch), px + (size_t)r * K_DIM + ch * 8);
        }
#pragma unroll
        for (int q = 0; q < 2; q++) {
            int idx = tid + q * 256;
            int r = idx >> 3, ch = idx & 7;
            cpasync16(st + 8192 + sw128(r, ch), pah + (size_t)r * K_DIM + ch * 8);
        }
    };

    load_stage(0, 0); CP_COMMIT();
    load_stage(1, 1); CP_COMMIT();

    for (int c = 0; c < 32; c++) {
        CP_WAIT1();
        __syncthreads();
        if (c + 2 < 32) load_stage(c + 2, (c + 2) % 3);
        CP_COMMIT();

        uint32_t st = sb + (uint32_t)(c % 3) * G_STAGE;
#pragma unroll
        for (int s = 0; s < 4; s++) {
            uint32_t xa[2][4], bh[4];
#pragma unroll
            for (int mi = 0; mi < 2; mi++) {
                int row = warp_m * 32 + mi * 16 + (lane & 15);
                int ch = s * 2 + (lane >> 4);
                LDSM4(xa[mi], st + sw128(row, ch));
            }
            {
                int nrow = warp_n * 16 + ((lane >> 4) << 3) + (lane & 7);
                int ch = s * 2 + ((lane >> 3) & 1);
                LDSM4(bh, st + 8192 + sw128(nrow, ch));
            }
#pragma unroll
            for (int mi = 0; mi < 2; mi++)
#pragma unroll
                for (int nt = 0; nt < 2; nt++)
                    MMA16816(acc[mi][nt], xa[mi], bh + nt * 2);
        }
    }

#pragma unroll
    for (int mi = 0; mi < 2; mi++)
#pragma unroll
        for (int h = 0; h < 2; h++) {
            int m = m0 + warp_m * 32 + mi * 16 + (lane >> 2) + h * 8;
            float mv = mask[(size_t)warp_n * M_TOTAL + m] * SCALE_F;
#pragma unroll
            for (int nt = 0; nt < 2; nt++) {
                float v0 = acc[mi][nt][2 * h + 0] * mv;
                float v1 = acc[mi][nt][2 * h + 1] * mv;
                size_t off = (size_t)m * JTOT + warp_n * 16 + nt * 8 + (lane & 3) * 2;
                *(uint32_t*)(g_g + off) = f16x2(v0, v1);
            }
        }
}

// ---------------- main fused GEMM: persistent, cross-tile pipeline ---------
// out = x@W^T + G@Bcat^T + b.  Tile 128x256, BK=64, 33 chunks/tile.
// 1024 tiles over 148 persistent CTAs; cp.async window rolls across tiles.
#define MSTAGE 49152
#define MSTAGES 4
#define MAIN_SMEM (MSTAGES * MSTAGE)
#define NCHUNK 33
#define NTILE  1024          // (M/128) * (N/256) = 128 * 8
#define PGRID  148

__global__ __launch_bounds__(256, 1) void main_gemm_kernel(
    const float* __restrict__ bias, float* __restrict__ out)
{
    extern __shared__ __align__(128) char smem[];
    const uint32_t sb = smem_u32(smem);
    const int tid = threadIdx.x, wid = tid >> 5, lane = tid & 31;
    const int warp_m = wid >> 2, warp_n = wid & 3;

    const int my_tiles = (NTILE - blockIdx.x + PGRID - 1) / PGRID;
    const int total_gc = my_tiles * NCHUNK;

    float acc[4][8][4];
#pragma unroll
    for (int i = 0; i < 4; i++)
#pragma unroll
        for (int j = 0; j < 8; j++)
#pragma unroll
            for (int p = 0; p < 4; p++) acc[i][j][p] = 0.f;

    // gc -> (tile-local chunk, tile coords)
    auto load_stage_g = [&](int gc, int st_i) {
        int k = gc / NCHUNK;
        int c = gc - k * NCHUNK;
        int t = blockIdx.x + k * PGRID;
        int m0 = (t >> 3) * 128;
        int n0 = (t & 7) * 256;
        uint32_t st = sb + (uint32_t)st_i * MSTAGE;
        const __half *pa, *pb;
        size_t strd;
        if (c < 32) {
            pa = g_xh + (size_t)m0 * K_DIM + c * 64;
            pb = g_wh + (size_t)n0 * K_DIM + c * 64;
            strd = K_DIM;
        } else {
            pa = g_g  + (size_t)m0 * JTOT;
            pb = g_bh + (size_t)n0 * JTOT;
            strd = JTOT;
        }
#pragma unroll
        for (int q = 0; q < 4; q++) {           // A: 128 rows x 8 chunks
            int idx = tid + q * 256;
            int r = idx >> 3, ch = idx & 7;
            cpasync16(st + sw128(r, ch), pa + (size_t)r * strd + ch * 8);
        }
#pragma unroll
        for (int q = 0; q < 8; q++) {           // B: 256 rows x 8 chunks
            int idx = tid + q * 256;
            int r = idx >> 3, ch = idx & 7;
            cpasync16(st + 16384 + sw128(r, ch), pb + (size_t)r * strd + ch * 8);
        }
    };

    load_stage_g(0, 0); CP_COMMIT();
    load_stage_g(1, 1); CP_COMMIT();
    load_stage_g(2, 2); CP_COMMIT();

    uint32_t ah[2][4][4], bh[2][4][4];

    auto load_frags = [&](uint32_t st, int s, int buf) {
#pragma unroll
        for (int mi = 0; mi < 4; mi++) {
            int row = warp_m * 64 + mi * 16 + (lane & 15);
            int ch = s * 2 + (lane >> 4);
            LDSM4(ah[buf][mi], st + sw128(row, ch));
        }
#pragma unroll
        for (int bj = 0; bj < 4; bj++) {
            int nrow = warp_n * 64 + bj * 16 + ((lane >> 4) << 3) + (lane & 7);
            int ch = s * 2 + ((lane >> 3) & 1);
            LDSM4(bh[buf][bj], st + 16384 + sw128(nrow, ch));
        }
    };

    for (int gc = 0; gc < total_gc; gc++) {
        CP_WAIT2();
        __syncthreads();
        if (gc + 3 < total_gc) load_stage_g(gc + 3, (gc + 3) % MSTAGES);
        CP_COMMIT();

        uint32_t st = sb + (uint32_t)(gc % MSTAGES) * MSTAGE;
        load_frags(st, 0, 0);
#pragma unroll
        for (int s = 0; s < 4; s++) {
            int cur = s & 1;
            if (s < 3) load_frags(st, s + 1, cur ^ 1);
#pragma unroll
            for (int mi = 0; mi < 4; mi++)
#pragma unroll
                for (int nt = 0; nt < 8; nt++)
                    MMA16816(acc[mi][nt], ah[cur][mi],
                             bh[cur][nt >> 1] + (nt & 1) * 2);
        }

        // ---- tile finished? epilogue + reset, pipeline keeps rolling ----
        int k = gc / NCHUNK;
        if (gc - k * NCHUNK == NCHUNK - 1) {
            int t = blockIdx.x + k * PGRID;
            int m0 = (t >> 3) * 128;
            int n0 = (t & 7) * 256;
#pragma unroll
            for (int mi = 0; mi < 4; mi++)
#pragma unroll
                for (int h = 0; h < 2; h++) {
                    int m = m0 + warp_m * 64 + mi * 16 + (lane >> 2) + h * 8;
                    float* po = out + (size_t)m * N_DIM + n0 + warp_n * 64;
#pragma unroll
                    for (int nt = 0; nt < 8; nt++) {
                        const float* pb =
                            bias + n0 + warp_n * 64 + nt * 8 + (lane & 3) * 2;
                        float2 bv = *(const float2*)pb;
                        float2 v;
                        v.x = acc[mi][nt][2 * h + 0] + bv.x;
                        v.y = acc[mi][nt][2 * h + 1] + bv.y;
                        *(float2*)(po + nt * 8 + (lane & 3) * 2) = v;
                        acc[mi][nt][2 * h + 0] = 0.f;
                        acc[mi][nt][2 * h + 1] = 0.f;
                    }
                }
        }
    }
}

// ---------------------------------------------------------------------------
extern "C" void kernel_launch(void* const* d_in, const int* in_sizes, int n_in,
                              void* d_out, int out_size)
{
    const float* x    = (const float*)d_in[0];
    const float* mask = (const float*)d_in[1];
    const float* W    = (const float*)d_in[2];
    const float* b    = (const float*)d_in[3];
    const float* A    = (const float*)d_in[4];
    const float* Bw   = (const float*)d_in[5];
    float* out        = (float*)d_out;

    cudaFuncSetAttribute(g_gemm_kernel,
                         cudaFuncAttributeMaxDynamicSharedMemorySize, G_SMEM);
    cudaFuncSetAttribute(main_gemm_kernel,
                         cudaFuncAttributeMaxDynamicSharedMemorySize, MAIN_SMEM);

    conv_xa_kernel<<<(CONV_XA_TOTAL + 255) / 256, 256>>>(x, A);

    g_gemm_kernel<<<G_BLOCKS + GCONV_BLOCKS, 256, G_SMEM>>>(mask, W, Bw);

    main_gemm_kernel<<<PGRID, 256, MAIN_SMEM>>>(b, out);
}

// round 17
// speedup vs baseline: 1.5434x; 1.5434x over previous
#include <cuda_runtime.h>
#include <cuda_fp16.h>
#include <cstdint>

#define M_TOTAL 16384
#define K_DIM   2048
#define N_DIM   2048
#define JTOT    64
#define SCALE_F 2.0f

// ---------------- device scratch ------------------------------------------
__device__ __align__(16) __half g_xh[(size_t)M_TOTAL * K_DIM];   // x fp16
__device__ __align__(16) __half g_wh[(size_t)N_DIM * K_DIM];     // W fp16
__device__ __align__(16) __half g_ah[(size_t)JTOT * K_DIM];      // Acat fp16
__device__ __align__(16) __half g_g [(size_t)M_TOTAL * JTOT];    // G fp16
__device__ __align__(16) __half g_bh[(size_t)N_DIM * JTOT];      // Bcat fp16

// ---------------- helpers --------------------------------------------------
static __device__ __forceinline__ uint32_t smem_u32(const void* p) {
    uint32_t a;
    asm("{ .reg .u64 t; cvta.to.shared.u64 t, %1; cvt.u32.u64 %0, t; }"
        : "=r"(a) : "l"(p));
    return a;
}
static __device__ __forceinline__ uint32_t f16x2(float a, float b) {
    uint32_t r;
    asm("cvt.rn.f16x2.f32 %0, %1, %2;" : "=r"(r) : "f"(b), "f"(a));
    return r;
}
static __device__ __forceinline__ void cpasync16(uint32_t dst, const void* src) {
    asm volatile("cp.async.cg.shared.global [%0], [%1], 16;"
                 :: "r"(dst), "l"(src) : "memory");
}
#define CP_COMMIT() asm volatile("cp.async.commit_group;" ::: "memory")
#define CP_WAIT2()  asm volatile("cp.async.wait_group 2;" ::: "memory")

#define LDSM4(r, addr)                                                       \
    asm volatile("ldmatrix.sync.aligned.m8n8.x4.shared.b16 {%0,%1,%2,%3}, [%4];" \
        : "=r"((r)[0]), "=r"((r)[1]), "=r"((r)[2]), "=r"((r)[3]) : "r"(addr))

#define MMA16816(c, a, b)                                                    \
    asm volatile(                                                            \
        "mma.sync.aligned.m16n8k16.row.col.f32.f16.f16.f32 "                 \
        "{%0,%1,%2,%3}, {%4,%5,%6,%7}, {%8,%9}, {%0,%1,%2,%3};"              \
        : "+f"((c)[0]), "+f"((c)[1]), "+f"((c)[2]), "+f"((c)[3])             \
        : "r"((a)[0]), "r"((a)[1]), "r"((a)[2]), "r"((a)[3]),                \
          "r"((b)[0]), "r"((b)[1]))

// 128B-row SW128 swizzle (BK=64 tiles)
static __device__ __forceinline__ uint32_t sw128(int row, int chunk) {
    return (uint32_t)(row * 128 + ((chunk ^ (row & 7)) << 4));
}

// ---------------- conversion sizes -----------------------------------------
#define NX8 4194304     // x:  uint4 items (8 fp32 each)
#define NW8 524288      // W:  uint4 items
#define NA8 16384       // A:  uint4 items
#define NB  131072      // Bw: scalar items
#define CONV_XA_TOTAL (NX8 + NA8)

static __device__ __forceinline__ uint4 cvt8s(const float4* s) {
    float4 v0 = __ldcs(s);
    float4 v1 = __ldcs(s + 1);
    uint4 o;
    o.x = f16x2(v0.x, v0.y);
    o.y = f16x2(v0.z, v0.w);
    o.z = f16x2(v1.x, v1.y);
    o.w = f16x2(v1.z, v1.w);
    return o;
}

// ---------------- conv kernel: x + Acat only (G's inputs) ------------------
__global__ void conv_xa_kernel(const float* __restrict__ x,
                               const float* __restrict__ A)
{
    int i = blockIdx.x * blockDim.x + threadIdx.x;
    if (i < NX8) {
        ((uint4*)g_xh)[i] = cvt8s(((const float4*)x) + 2 * (size_t)i);
        return;
    }
    i -= NX8;
    if (i < NA8)
        ((uint4*)g_ah)[i] = cvt8s(((const float4*)A) + 2 * (size_t)i);
}

// ---------------- G kernel + embedded W/Bw converter blocks ----------------
// Blocks [0,256): G = (x @ Acat^T) * SCALE * mask  (BM=64, BK=64, 32 chunks)
// Blocks [256, 256+GCONV): grid-stride conversion of W and Bw
#define G_BLOCKS     256
#define GCONV_BLOCKS 188
#define G_STAGE   16384
#define G_STAGES  4
#define G_SMEM    (G_STAGES * G_STAGE)

__global__ __launch_bounds__(256, 3) void g_gemm_kernel(
    const float* __restrict__ mask,
    const float* __restrict__ W,
    const float* __restrict__ Bw)
{
    extern __shared__ __align__(128) char smem[];
    const int tid = threadIdx.x;

    if (blockIdx.x >= G_BLOCKS) {
        const int stride = GCONV_BLOCKS * 256;
        int base = (blockIdx.x - G_BLOCKS) * 256 + tid;
        for (int i = base; i < NW8; i += stride)
            ((uint4*)g_wh)[i] = cvt8s(((const float4*)W) + 2 * (size_t)i);
        for (int i = base; i < NB; i += stride) {
            int na = i >> 15;
            int n  = (i >> 4) & 2047;
            int r  = i & 15;
            g_bh[(size_t)n * JTOT + na * 16 + r] = __float2half_rn(__ldcs(Bw + i));
        }
        return;
    }

    const uint32_t sb = smem_u32(smem);
    const int wid = tid >> 5, lane = tid & 31;
    const int warp_m = wid >> 2, warp_n = wid & 3;
    const int m0 = blockIdx.x * 64;

    float acc[2][2][4];
#pragma unroll
    for (int i = 0; i < 2; i++)
#pragma unroll
        for (int j = 0; j < 2; j++)
#pragma unroll
            for (int p = 0; p < 4; p++) acc[i][j][p] = 0.f;

    auto load_stage = [&](int c, int st_i) {
        uint32_t st = sb + (uint32_t)st_i * G_STAGE;
        const __half* px  = g_xh + (size_t)m0 * K_DIM + c * 64;
        const __half* pah = g_ah + (size_t)c * 64;
#pragma unroll
        for (int q = 0; q < 2; q++) {
            int idx = tid + q * 256;
            int r = idx >> 3, ch = idx & 7;
            cpasync16(st + sw128(r, ch), px + (size_t)r * K_DIM + ch * 8);
        }
#pragma unroll
        for (int q = 0; q < 2; q++) {
            int idx = tid + q * 256;
            int r = idx >> 3, ch = idx & 7;
            cpasync16(st + 8192 + sw128(r, ch), pah + (size_t)r * K_DIM + ch * 8);
        }
    };

    load_stage(0, 0); CP_COMMIT();
    load_stage(1, 1); CP_COMMIT();
    load_stage(2, 2); CP_COMMIT();

    for (int c = 0; c < 32; c++) {
        CP_WAIT2();
        __syncthreads();
        if (c + 3 < 32) load_stage(c + 3, (c + 3) % G_STAGES);
        CP_COMMIT();

        uint32_t st = sb + (uint32_t)(c % G_STAGES) * G_STAGE;
#pragma unroll
        for (int s = 0; s < 4; s++) {
            uint32_t xa[2][4], bh[4];
#pragma unroll
            for (int mi = 0; mi < 2; mi++) {
                int row = warp_m * 32 + mi * 16 + (lane & 15);
                int ch = s * 2 + (lane >> 4);
                LDSM4(xa[mi], st + sw128(row, ch));
            }
            {
                int nrow = warp_n * 16 + ((lane >> 4) << 3) + (lane & 7);
                int ch = s * 2 + ((lane >> 3) & 1);
                LDSM4(bh, st + 8192 + sw128(nrow, ch));
            }
#pragma unroll
            for (int mi = 0; mi < 2; mi++)
#pragma unroll
                for (int nt = 0; nt < 2; nt++)
                    MMA16816(acc[mi][nt], xa[mi], bh + nt * 2);
        }
    }

#pragma unroll
    for (int mi = 0; mi < 2; mi++)
#pragma unroll
        for (int h = 0; h < 2; h++) {
            int m = m0 + warp_m * 32 + mi * 16 + (lane >> 2) + h * 8;
            float mv = mask[(size_t)warp_n * M_TOTAL + m] * SCALE_F;
#pragma unroll
            for (int nt = 0; nt < 2; nt++) {
                float v0 = acc[mi][nt][2 * h + 0] * mv;
                float v1 = acc[mi][nt][2 * h + 1] * mv;
                size_t off = (size_t)m * JTOT + warp_n * 16 + nt * 8 + (lane & 3) * 2;
                *(uint32_t*)(g_g + off) = f16x2(v0, v1);
            }
        }
}

// ---------------- main fused GEMM: 4-stage pipeline (R15 proven) -----------
// out = x@W^T + G@Bcat^T + b.  BM=128, BN=256, BK=64, 33 chunks.
#define MSTAGE 49152
#define MSTAGES 4
#define MAIN_SMEM (MSTAGES * MSTAGE)
#define NCHUNK 33

__global__ __launch_bounds__(256, 1) void main_gemm_kernel(
    const float* __restrict__ bias, float* __restrict__ out)
{
    extern __shared__ __align__(128) char smem[];
    const uint32_t sb = smem_u32(smem);
    const int tid = threadIdx.x, wid = tid >> 5, lane = tid & 31;
    const int warp_m = wid >> 2, warp_n = wid & 3;
    const int n0 = blockIdx.x * 256, m0 = blockIdx.y * 128;

    float acc[4][8][4];
#pragma unroll
    for (int i = 0; i < 4; i++)
#pragma unroll
        for (int j = 0; j < 8; j++)
#pragma unroll
            for (int p = 0; p < 4; p++) acc[i][j][p] = 0.f;

    auto load_stage = [&](int c, int st_i) {
        uint32_t st = sb + (uint32_t)st_i * MSTAGE;
        const __half *pa, *pb;
        size_t strd;
        if (c < 32) {
            pa = g_xh + (size_t)m0 * K_DIM + c * 64;
            pb = g_wh + (size_t)n0 * K_DIM + c * 64;
            strd = K_DIM;
        } else {
            pa = g_g  + (size_t)m0 * JTOT;
            pb = g_bh + (size_t)n0 * JTOT;
            strd = JTOT;
        }
#pragma unroll
        for (int q = 0; q < 4; q++) {           // A: 128 rows x 8 chunks
            int idx = tid + q * 256;
            int r = idx >> 3, ch = idx & 7;
            cpasync16(st + sw128(r, ch), pa + (size_t)r * strd + ch * 8);
        }
#pragma unroll
        for (int q = 0; q < 8; q++) {           // B: 256 rows x 8 chunks
            int idx = tid + q * 256;
            int r = idx >> 3, ch = idx & 7;
            cpasync16(st + 16384 + sw128(r, ch), pb + (size_t)r * strd + ch * 8);
        }
    };

    load_stage(0, 0); CP_COMMIT();
    load_stage(1, 1); CP_COMMIT();
    load_stage(2, 2); CP_COMMIT();

    uint32_t ah[2][4][4], bh[2][4][4];

    auto load_frags = [&](uint32_t st, int s, int buf) {
#pragma unroll
        for (int mi = 0; mi < 4; mi++) {
            int row = warp_m * 64 + mi * 16 + (lane & 15);
            int ch = s * 2 + (lane >> 4);
            LDSM4(ah[buf][mi], st + sw128(row, ch));
        }
#pragma unroll
        for (int bj = 0; bj < 4; bj++) {
            int nrow = warp_n * 64 + bj * 16 + ((lane >> 4) << 3) + (lane & 7);
            int ch = s * 2 + ((lane >> 3) & 1);
            LDSM4(bh[buf][bj], st + 16384 + sw128(nrow, ch));
        }
    };

    for (int c = 0; c < NCHUNK; c++) {
        CP_WAIT2();
        __syncthreads();
        if (c + 3 < NCHUNK) load_stage(c + 3, (c + 3) % MSTAGES);
        CP_COMMIT();

        uint32_t st = sb + (uint32_t)(c % MSTAGES) * MSTAGE;
        load_frags(st, 0, 0);
#pragma unroll
        for (int s = 0; s < 4; s++) {
            int cur = s & 1;
            if (s < 3) load_frags(st, s + 1, cur ^ 1);
#pragma unroll
            for (int mi = 0; mi < 4; mi++)
#pragma unroll
                for (int nt = 0; nt < 8; nt++)
                    MMA16816(acc[mi][nt], ah[cur][mi],
                             bh[cur][nt >> 1] + (nt & 1) * 2);
        }
    }

    // epilogue: + bias, fp32 out
    float2 bfrag[8];
#pragma unroll
    for (int nt = 0; nt < 8; nt++)
        bfrag[nt] = *(const float2*)(bias + n0 + warp_n * 64 + nt * 8 + (lane & 3) * 2);

#pragma unroll
    for (int mi = 0; mi < 4; mi++)
#pragma unroll
        for (int h = 0; h < 2; h++) {
            int m = m0 + warp_m * 64 + mi * 16 + (lane >> 2) + h * 8;
            float* po = out + (size_t)m * N_DIM + n0 + warp_n * 64;
#pragma unroll
            for (int nt = 0; nt < 8; nt++) {
                float2 v;
                v.x = acc[mi][nt][2 * h + 0] + bfrag[nt].x;
                v.y = acc[mi][nt][2 * h + 1] + bfrag[nt].y;
                *(float2*)(po + nt * 8 + (lane & 3) * 2) = v;
            }
        }
}

// ---------------------------------------------------------------------------
extern "C" void kernel_launch(void* const* d_in, const int* in_sizes, int n_in,
                              void* d_out, int out_size)
{
    const float* x    = (const float*)d_in[0];
    const float* mask = (const float*)d_in[1];
    const float* W    = (const float*)d_in[2];
    const float* b    = (const float*)d_in[3];
    const float* A    = (const float*)d_in[4];
    const float* Bw   = (const float*)d_in[5];
    float* out        = (float*)d_out;

    cudaFuncSetAttribute(g_gemm_kernel,
                         cudaFuncAttributeMaxDynamicSharedMemorySize, G_SMEM);
    cudaFuncSetAttribute(main_gemm_kernel,
                         cudaFuncAttributeMaxDynamicSharedMemorySize, MAIN_SMEM);

    conv_xa_kernel<<<(CONV_XA_TOTAL + 255) / 256, 256>>>(x, A);

    g_gemm_kernel<<<G_BLOCKS + GCONV_BLOCKS, 256, G_SMEM>>>(mask, W, Bw);

    dim3 grid(N_DIM / 256, M_TOTAL / 128);
    main_gemm_kernel<<<grid, 256, MAIN_SMEM>>>(b, out);
}